// round 13
// baseline (speedup 1.0000x reference)
#include <cuda_runtime.h>
#include <cuda_bf16.h>

#define TOTAL_N 1000000
#define DIM     128
#define BATCH   4096
#define WIN     256

__global__ __launch_bounds__(128, 8)
void coord_pool_kernel(const float* __restrict__ mu,
                       const float* __restrict__ sigma,
                       const float* __restrict__ params,
                       float* __restrict__ out,
                       int write_starts)
{
    __shared__ float  sw[WIN];         // normalized weights
    __shared__ double warpsum[4];
    __shared__ double s_inv;
    __shared__ float4 red4[4 * DIM / 4];

    const int b    = blockIdx.x;
    const int tid  = threadIdx.x;
    const int lane = tid & 31;
    const int wid  = tid >> 5;

    // ---- replicate reference f32 chain EXACTLY ----
    // center_idx = mu * 999999 : single f32 FMUL rounding (intrinsic blocks
    // FFMA contraction -- this rounding is the whole ballgame).
    const float center_f = __fmul_rn(mu[b], (float)(TOTAL_N - 1));
    // start = clip(center - 128, 0, 999744).astype(int32), all in f32
    float startf = __fadd_rn(center_f, -(float)(WIN / 2));
    startf = fminf(fmaxf(startf, 0.0f), (float)(TOTAL_N - WIN));
    const int start = (int)startf;

    // sigma + 1e-6 in f32, then 2*s^2 in f32 (rounded like the reference)
    const float sf   = __fadd_rn(sigma[b], 1e-6f);
    const float den  = __fmul_rn(2.0f, __fmul_rn(sf, sf));

    // ---- weights: arg in f32 (ref-faithful), exp+sum in f64 (accurate) ----
    double sdw_local[2];
    double partial = 0.0;
    #pragma unroll
    for (int k = 0; k < 2; k++) {
        const int w   = tid + k * 128;
        // d = (start+w) - center : exact f32 subtraction of the f32 center
        const float df  = __fadd_rn((float)(start + w), -center_f);
        const float arg = __fdiv_rn(-__fmul_rn(df, df), den);
        const double e  = exp((double)arg);
        sdw_local[k] = e;
        partial += e;
    }
    #pragma unroll
    for (int o = 16; o > 0; o >>= 1)
        partial += __shfl_xor_sync(0xffffffff, partial, o);
    if (lane == 0) warpsum[wid] = partial;
    __syncthreads();
    if (tid == 0)
        s_inv = 1.0 / ((warpsum[0] + warpsum[1] + warpsum[2] + warpsum[3]) + 1e-6);
    __syncthreads();
    {
        const double inv = s_inv;
        sw[tid]       = (float)(sdw_local[0] * inv);
        sw[tid + 128] = (float)(sdw_local[1] * inv);
    }
    __syncthreads();

    // ---- gather-reduce (f32, bandwidth-critical) ----
    // Warp `wid` owns rows wid, wid+4, ...: 32 lanes x float4 = full 512B row
    // per warp-level load; unroll 8 -> MLP=8 covers DRAM latency.
    const float4* __restrict__ p4 = (const float4*)params;
    const size_t rowbase = (size_t)start * (DIM / 4);

    float4 acc = make_float4(0.f, 0.f, 0.f, 0.f);
    #pragma unroll 8
    for (int w = wid; w < WIN; w += 4) {
        const float4 v = __ldg(&p4[rowbase + (size_t)w * (DIM / 4) + lane]);
        const float wt = sw[w];
        acc.x = fmaf(wt, v.x, acc.x);
        acc.y = fmaf(wt, v.y, acc.y);
        acc.z = fmaf(wt, v.z, acc.z);
        acc.w = fmaf(wt, v.w, acc.w);
    }

    red4[wid * 32 + lane] = acc;
    __syncthreads();

    const float* red = (const float*)red4;
    out[(size_t)b * DIM + tid] =
        red[tid] + red[128 + tid] + red[256 + tid] + red[384 + tid];

    if (write_starts && tid == 0)
        out[(size_t)BATCH * DIM + b] = (float)start;
}

extern "C" void kernel_launch(void* const* d_in, const int* in_sizes, int n_in,
                              void* d_out, int out_size) {
    int big = 0;
    for (int i = 1; i < n_in; i++)
        if (in_sizes[i] > in_sizes[big]) big = i;

    const float* params = (const float*)d_in[big];
    const float* mu = nullptr;
    const float* sigma = nullptr;
    for (int i = 0; i < n_in; i++) {
        if (i == big) continue;
        if (mu == nullptr) mu = (const float*)d_in[i];
        else if (sigma == nullptr) sigma = (const float*)d_in[i];
    }

    float* out = (float*)d_out;
    const int write_starts = (out_size >= BATCH * DIM + BATCH) ? 1 : 0;

    coord_pool_kernel<<<BATCH, 128>>>(mu, sigma, params, out, write_starts);
}

// round 14
// speedup vs baseline: 1.2707x; 1.2707x over previous
#include <cuda_runtime.h>
#include <cuda_bf16.h>

#define TOTAL_N 1000000
#define DIM     128
#define BATCH   4096
#define WIN     256

__global__ __launch_bounds__(128)
void coord_pool_kernel(const float* __restrict__ mu,
                       const float* __restrict__ sigma,
                       const float* __restrict__ params,
                       float* __restrict__ out,
                       int write_starts)
{
    __shared__ float  sw[WIN];         // normalized weights
    __shared__ float  warpsum[4];
    __shared__ float  s_den;
    __shared__ float4 red4[4 * DIM / 4];

    const int b    = blockIdx.x;
    const int tid  = threadIdx.x;
    const int lane = tid & 31;
    const int wid  = tid >> 5;

    // ---- ref-faithful f32 chain (LOAD-BEARING: do not alter rounding) ----
    // center_idx = mu * 999999 : single f32 FMUL rounding.
    const float center_f = __fmul_rn(mu[b], (float)(TOTAL_N - 1));
    float startf = __fadd_rn(center_f, -(float)(WIN / 2));
    startf = fminf(fmaxf(startf, 0.0f), (float)(TOTAL_N - WIN));
    const int start = (int)startf;

    const float sf  = __fadd_rn(sigma[b], 1e-6f);
    const float den = __fmul_rn(2.0f, __fmul_rn(sf, sf));

    // ---- weights entirely in f32 (arg bit-identical to R13's) ----
    float e0, e1;
    float partial;
    {
        const float d0 = __fadd_rn((float)(start + tid), -center_f);
        const float a0 = __fdiv_rn(-__fmul_rn(d0, d0), den);
        e0 = expf(a0);
        const float d1 = __fadd_rn((float)(start + tid + 128), -center_f);
        const float a1 = __fdiv_rn(-__fmul_rn(d1, d1), den);
        e1 = expf(a1);
        partial = e0 + e1;
    }
    #pragma unroll
    for (int o = 16; o > 0; o >>= 1)
        partial += __shfl_xor_sync(0xffffffff, partial, o);
    if (lane == 0) warpsum[wid] = partial;
    __syncthreads();
    if (tid == 0)
        s_den = (warpsum[0] + warpsum[1] + warpsum[2] + warpsum[3]) + 1e-6f;
    __syncthreads();
    {
        const float d = s_den;
        sw[tid]       = __fdiv_rn(e0, d);
        sw[tid + 128] = __fdiv_rn(e1, d);
    }
    __syncthreads();

    // ---- gather-reduce (f32, bandwidth-critical) ----
    // Warp `wid` owns rows wid, wid+4, ...: 32 lanes x float4 = full 512B row
    // per warp-level load; unroll 8 -> 8 outstanding LDG.128 per warp.
    const float4* __restrict__ p4 = (const float4*)params;
    const size_t rowbase = (size_t)start * (DIM / 4);

    float4 acc = make_float4(0.f, 0.f, 0.f, 0.f);
    #pragma unroll 8
    for (int w = wid; w < WIN; w += 4) {
        const float4 v = __ldg(&p4[rowbase + (size_t)w * (DIM / 4) + lane]);
        const float wt = sw[w];
        acc.x = fmaf(wt, v.x, acc.x);
        acc.y = fmaf(wt, v.y, acc.y);
        acc.z = fmaf(wt, v.z, acc.z);
        acc.w = fmaf(wt, v.w, acc.w);
    }

    red4[wid * 32 + lane] = acc;
    __syncthreads();

    const float* red = (const float*)red4;
    out[(size_t)b * DIM + tid] =
        red[tid] + red[128 + tid] + red[256 + tid] + red[384 + tid];

    if (write_starts && tid == 0)
        out[(size_t)BATCH * DIM + b] = (float)start;
}

extern "C" void kernel_launch(void* const* d_in, const int* in_sizes, int n_in,
                              void* d_out, int out_size) {
    int big = 0;
    for (int i = 1; i < n_in; i++)
        if (in_sizes[i] > in_sizes[big]) big = i;

    const float* params = (const float*)d_in[big];
    const float* mu = nullptr;
    const float* sigma = nullptr;
    for (int i = 0; i < n_in; i++) {
        if (i == big) continue;
        if (mu == nullptr) mu = (const float*)d_in[i];
        else if (sigma == nullptr) sigma = (const float*)d_in[i];
    }

    float* out = (float*)d_out;
    const int write_starts = (out_size >= BATCH * DIM + BATCH) ? 1 : 0;

    coord_pool_kernel<<<BATCH, 128>>>(mu, sigma, params, out, write_starts);
}